// round 1
// baseline (speedup 1.0000x reference)
#include <cuda_runtime.h>
#include <cuda_bf16.h>

// ---------------- problem constants ----------------
#define NN    65536      // nodes
#define HIDD  256
#define BB    64         // batches
#define EPER  8192       // edges per batch
#define ET    524288     // total edges
#define NRES  4096       // kept edges per batch
#define EC    262144     // total causal (=conf) edges

// ---------------- output offsets (float32 elements) ----------------
#define OFF_CX   0ul
#define OFF_CEI  16777216ul
#define OFF_CW   17301504ul
#define OFF_CB   17563648ul
#define OFF_FX   17629184ul
#define OFF_FEI  34406400ul
#define OFF_FW   34930688ul
#define OFF_FB   35192832ul
#define OFF_ES   35258368ul

// ---------------- scratch (static device globals; no allocation) ----------------
__device__ float g_t[NN * HIDD];   // agg output
__device__ float g_u[NN * HIDD];   // after linear1+relu
__device__ float g_h[NN * HIDD];   // layer output h
__device__ int   g_deg[NN + 1];    // CSR offsets
__device__ int   g_pos[NN];        // fill cursors
__device__ int   g_col[ET];        // CSR adjacency (cols)
__device__ float g_ssrc[NN];
__device__ float g_sdst[NN];
__device__ int   g_cei[2 * EC];    // causal edges (global node ids): [0,EC)=row, [EC,2EC)=col
__device__ int   g_fei[2 * EC];    // conf edges
__device__ int   g_pres_c[NN];
__device__ int   g_pres_f[NN];
__device__ int   g_rank_c[NN];
__device__ int   g_rank_f[NN];
__device__ int   g_list_c[NN];
__device__ int   g_list_f[NN];
__device__ int   g_cnt_c;
__device__ int   g_cnt_f;

// ---------------- kernels ----------------

__global__ void k_zero_misc() {
    int i = blockIdx.x * blockDim.x + threadIdx.x;
    if (i <= NN) g_deg[i] = 0;
    if (i < NN) { g_pres_c[i] = 0; g_pres_f[i] = 0; }
}

__global__ void k_count_deg(const int* __restrict__ ei) {
    int e = blockIdx.x * blockDim.x + threadIdx.x;
    if (e < ET) atomicAdd(&g_deg[ei[e] + 1], 1);
}

// single-block inclusive scan of g_deg[0..NN] -> start offsets; g_deg[v] = start(v)
__global__ __launch_bounds__(1024) void k_scan_deg() {
    __shared__ int part[1024];
    const int t = threadIdx.x;
    const int CH = 65;                 // 1024*65 >= 65537
    int base = t * CH;
    int n = 0;
    if (base < NN + 1) { n = NN + 1 - base; if (n > CH) n = CH; }
    int s = 0;
    for (int i = 0; i < n; i++) s += g_deg[base + i];
    part[t] = s;
    __syncthreads();
    for (int off = 1; off < 1024; off <<= 1) {
        int v = (t >= off) ? part[t - off] : 0;
        __syncthreads();
        part[t] += v;
        __syncthreads();
    }
    int run = part[t] - s;   // exclusive prefix
    for (int i = 0; i < n; i++) {
        run += g_deg[base + i];
        g_deg[base + i] = run;   // inclusive scan => start offset of node index
    }
}

__global__ void k_copy_pos() {
    int v = blockIdx.x * blockDim.x + threadIdx.x;
    if (v < NN) g_pos[v] = g_deg[v];
}

__global__ void k_fill_csr(const int* __restrict__ ei) {
    int e = blockIdx.x * blockDim.x + threadIdx.x;
    if (e < ET) {
        int r = ei[e];
        int p = atomicAdd(&g_pos[r], 1);
        g_col[p] = ei[ET + e];
    }
}

// t[v] = h[v] + sum_{nb in CSR[v]} h[nb]   (2 nodes / 128-thread block, float4 lanes)
__global__ __launch_bounds__(128) void k_agg(const float* __restrict__ hin,
                                             float* __restrict__ tout) {
    int v = blockIdx.x * 2 + (threadIdx.x >> 6);
    int lane = threadIdx.x & 63;
    const float4* H = (const float4*)hin;
    float4 acc = H[(size_t)v * 64 + lane];
    int s = g_deg[v], e = g_deg[v + 1];
    for (int i = s; i < e; i++) {
        int nb = g_col[i];
        float4 x = H[(size_t)nb * 64 + lane];
        acc.x += x.x; acc.y += x.y; acc.z += x.z; acc.w += x.w;
    }
    ((float4*)tout)[(size_t)v * 64 + lane] = acc;
}

// C = relu(A @ W + bias); A: M x 256, W: 256 x 256 (row-major K x N)
// block tile 128x64, K-tile 16, 256 threads, 8x4 per thread
#define BM 128
#define BN 64
#define BK 16
__global__ __launch_bounds__(256) void k_gemm_bias_relu(const float* __restrict__ A,
                                                        const float* __restrict__ W,
                                                        const float* __restrict__ bias,
                                                        float* __restrict__ C) {
    __shared__ float As[BK][BM];
    __shared__ float Ws[BK][BN];
    const int bm = blockIdx.x;
    const int bn = blockIdx.y;
    const int t = threadIdx.x;
    const int tx = t & 15;    // 16 column groups * 4
    const int ty = t >> 4;    // 16 row groups * 8

    const float* Ablk = A + (size_t)bm * BM * 256;

    float acc[8][4];
#pragma unroll
    for (int m = 0; m < 8; m++)
#pragma unroll
        for (int n = 0; n < 4; n++) acc[m][n] = 0.f;

    for (int k0 = 0; k0 < 256; k0 += BK) {
        // load A tile (128x16) transposed into As[16][128]
#pragma unroll
        for (int i = 0; i < 2; i++) {
            int q = t + i * 256;          // float4 index, 0..511
            int arow = q >> 2;            // 0..127
            int acg = q & 3;              // 0..3 (col group of 4)
            float4 v = *(const float4*)&Ablk[(size_t)arow * 256 + k0 + acg * 4];
            As[acg * 4 + 0][arow] = v.x;
            As[acg * 4 + 1][arow] = v.y;
            As[acg * 4 + 2][arow] = v.z;
            As[acg * 4 + 3][arow] = v.w;
        }
        // load W tile (16x64)
        {
            int wr = t >> 4;              // 0..15
            int wc = t & 15;              // 0..15 (float4 col group)
            float4 v = *(const float4*)&W[(size_t)(k0 + wr) * 256 + bn * BN + wc * 4];
            *(float4*)&Ws[wr][wc * 4] = v;
        }
        __syncthreads();

#pragma unroll
        for (int k = 0; k < BK; k++) {
            float4 a0 = *(const float4*)&As[k][ty * 8];
            float4 a1 = *(const float4*)&As[k][ty * 8 + 4];
            float4 wv = *(const float4*)&Ws[k][tx * 4];
            float a[8] = {a0.x, a0.y, a0.z, a0.w, a1.x, a1.y, a1.z, a1.w};
            float w[4] = {wv.x, wv.y, wv.z, wv.w};
#pragma unroll
            for (int m = 0; m < 8; m++)
#pragma unroll
                for (int n = 0; n < 4; n++) acc[m][n] += a[m] * w[n];
        }
        __syncthreads();
    }

    float4 bv = *(const float4*)&bias[bn * BN + tx * 4];
#pragma unroll
    for (int m = 0; m < 8; m++) {
        int row = bm * BM + ty * 8 + m;
        float4 r;
        r.x = fmaxf(acc[m][0] + bv.x, 0.f);
        r.y = fmaxf(acc[m][1] + bv.y, 0.f);
        r.z = fmaxf(acc[m][2] + bv.z, 0.f);
        r.w = fmaxf(acc[m][3] + bv.w, 0.f);
        *(float4*)&C[(size_t)row * 256 + bn * BN + tx * 4] = r;
    }
}

// s_src[v] = h[v] . w[:256], s_dst[v] = h[v] . w[256:]; one warp per node
__global__ __launch_bounds__(256) void k_score(const float* __restrict__ h,
                                               const float* __restrict__ wsc) {
    int gw = (blockIdx.x * blockDim.x + threadIdx.x) >> 5;
    int lane = threadIdx.x & 31;
    if (gw >= NN) return;
    const float4* H = (const float4*)(h + (size_t)gw * 256);
    const float4* W1 = (const float4*)wsc;
    const float4* W2 = (const float4*)(wsc + 256);
    float s1 = 0.f, s2 = 0.f;
#pragma unroll
    for (int i = lane; i < 64; i += 32) {
        float4 hv = H[i], w1 = W1[i], w2 = W2[i];
        s1 += hv.x * w1.x + hv.y * w1.y + hv.z * w1.z + hv.w * w1.w;
        s2 += hv.x * w2.x + hv.y * w2.y + hv.z * w2.z + hv.w * w2.w;
    }
#pragma unroll
    for (int o = 16; o; o >>= 1) {
        s1 += __shfl_xor_sync(0xffffffffu, s1, o);
        s2 += __shfl_xor_sync(0xffffffffu, s2, o);
    }
    if (lane == 0) { g_ssrc[gw] = s1; g_sdst[gw] = s2; }
}

__global__ void k_edge_score(const int* __restrict__ ei,
                             const float* __restrict__ bsc,
                             float* __restrict__ out) {
    int e = blockIdx.x * blockDim.x + threadIdx.x;
    if (e < ET) {
        out[OFF_ES + e] = g_ssrc[ei[e]] + g_sdst[ei[ET + e]] + bsc[0];
    }
}

// one block per batch: stable descending sort of 8192 scores (bitonic on
// (flipped_score, index) 48-bit key in static smem), then split top-4096/rest.
__global__ __launch_bounds__(1024) void k_sort_select(const float* __restrict__ es,
                                                      const int* __restrict__ ei,
                                                      float* __restrict__ out) {
    __shared__ unsigned int   kh[EPER];   // 32 KB
    __shared__ unsigned short kl[EPER];   // 16 KB
    const int b = blockIdx.x;
    const int tid = threadIdx.x;

    for (int i = tid; i < EPER; i += 1024) {
        float s = es[b * EPER + i];
        unsigned u = __float_as_uint(s);
        u = (u & 0x80000000u) ? ~u : (u | 0x80000000u);  // ascending-orderable
        kh[i] = ~u;                                       // ascending kh == descending score
        kl[i] = (unsigned short)i;                        // tie-break: smaller index first
    }
    __syncthreads();

    for (int k = 2; k <= EPER; k <<= 1) {
        for (int j = k >> 1; j > 0; j >>= 1) {
            for (int i = tid; i < EPER; i += 1024) {
                int l = i ^ j;
                if (l > i) {
                    bool up = ((i & k) == 0);
                    unsigned ah = kh[i], bh = kh[l];
                    unsigned short al = kl[i], bl = kl[l];
                    bool agtb = (ah > bh) || (ah == bh && al > bl);
                    if (agtb == up) {
                        kh[i] = bh; kh[l] = ah;
                        kl[i] = bl; kl[l] = al;
                    }
                }
            }
            __syncthreads();
        }
    }

    for (int i = tid; i < EPER; i += 1024) {
        int idx = kl[i];
        int ge = b * EPER + idx;
        float s = es[ge];
        int r = ei[ge];
        int c = ei[ET + ge];
        if (i < NRES) {
            int p = b * NRES + i;
            out[OFF_CW + p] = s;
            g_cei[p] = r; g_cei[EC + p] = c;
            g_pres_c[r] = 1; g_pres_c[c] = 1;
        } else {
            int p = b * NRES + (i - NRES);
            out[OFF_FW + p] = -s;
            g_fei[p] = r; g_fei[EC + p] = c;
            g_pres_f[r] = 1; g_pres_f[c] = 1;
        }
    }
}

// single-block compaction: rank + sorted-unique list + batch output (valid part)
__global__ __launch_bounds__(1024) void k_compact(int which,
                                                  const int* __restrict__ batch_in,
                                                  float* __restrict__ out_b) {
    __shared__ int part[1024];
    const int* pres = which ? g_pres_f : g_pres_c;
    int* rank = which ? g_rank_f : g_rank_c;
    int* list = which ? g_list_f : g_list_c;
    int* cnt = which ? &g_cnt_f : &g_cnt_c;

    const int t = threadIdx.x;
    const int base = t * 64;
    int s = 0;
    for (int i = 0; i < 64; i++) s += pres[base + i];
    part[t] = s;
    __syncthreads();
    for (int off = 1; off < 1024; off <<= 1) {
        int v = (t >= off) ? part[t - off] : 0;
        __syncthreads();
        part[t] += v;
        __syncthreads();
    }
    int run = part[t] - s;
    for (int i = 0; i < 64; i++) {
        int v = base + i;
        if (pres[v]) {
            rank[v] = run;
            list[run] = v;
            out_b[run] = (float)batch_in[v];
            run++;
        }
    }
    if (t == 1023) *cnt = part[1023];
}

__global__ void k_fill_batch(int which, float* __restrict__ out_b) {
    int i = blockIdx.x * blockDim.x + threadIdx.x;
    int c = which ? g_cnt_f : g_cnt_c;
    if (i < NN && i >= c) out_b[i] = -1.0f;
}

// causal_x / conf_x gather (float4 granularity)
__global__ void k_gather_x(int which, const float* __restrict__ h,
                           float* __restrict__ outx) {
    int gid = blockIdx.x * blockDim.x + threadIdx.x;   // NN*64 float4s
    if (gid >= NN * 64) return;
    int row = gid >> 6;
    int c = gid & 63;
    int cnt = which ? g_cnt_f : g_cnt_c;
    float4 v;
    if (row < cnt) {
        int src = which ? g_list_f[row] : g_list_c[row];
        v = ((const float4*)h)[(size_t)src * 64 + c];
    } else {
        v = make_float4(0.f, 0.f, 0.f, 0.f);
    }
    ((float4*)outx)[gid] = v;
}

__global__ void k_ei_rel(int which, float* __restrict__ dst) {
    int k = blockIdx.x * blockDim.x + threadIdx.x;
    if (k < 2 * EC) {
        const int* eib = which ? g_fei : g_cei;
        const int* rank = which ? g_rank_f : g_rank_c;
        dst[k] = (float)rank[eib[k]];
    }
}

// ---------------- launch ----------------
extern "C" void kernel_launch(void* const* d_in, const int* in_sizes, int n_in,
                              void* d_out, int out_size) {
    (void)in_sizes; (void)n_in; (void)out_size;
    const float* x    = (const float*)d_in[0];
    const int*   ei   = (const int*)d_in[1];
    const int*   batch= (const int*)d_in[2];
    const float* W11  = (const float*)d_in[3];
    const float* b11  = (const float*)d_in[4];
    const float* W12  = (const float*)d_in[5];
    const float* b12  = (const float*)d_in[6];
    const float* W21  = (const float*)d_in[7];
    const float* b21  = (const float*)d_in[8];
    const float* W22  = (const float*)d_in[9];
    const float* b22  = (const float*)d_in[10];
    const float* wsc  = (const float*)d_in[11];
    const float* bsc  = (const float*)d_in[12];
    float* out = (float*)d_out;

    // --- CSR build ---
    k_zero_misc<<<(NN + 1 + 255) / 256, 256>>>();
    k_count_deg<<<ET / 256, 256>>>(ei);
    k_scan_deg<<<1, 1024>>>();
    k_copy_pos<<<NN / 256, 256>>>();
    k_fill_csr<<<ET / 256, 256>>>(ei);

    dim3 ggrid(NN / BM, 256 / BN);

    // --- GIN layer 1 ---
    k_agg<<<NN / 2, 128>>>(x, g_t);
    k_gemm_bias_relu<<<ggrid, 256>>>(g_t, W11, b11, g_u);
    k_gemm_bias_relu<<<ggrid, 256>>>(g_u, W12, b12, g_h);

    // --- GIN layer 2 ---
    k_agg<<<NN / 2, 128>>>(g_h, g_t);
    k_gemm_bias_relu<<<ggrid, 256>>>(g_t, W21, b21, g_u);
    k_gemm_bias_relu<<<ggrid, 256>>>(g_u, W22, b22, g_h);

    // --- edge scores ---
    k_score<<<(NN * 32) / 256, 256>>>(g_h, wsc);
    k_edge_score<<<ET / 256, 256>>>(ei, bsc, out);

    // --- per-batch stable sort + top-k split ---
    k_sort_select<<<BB, 1024>>>(out + OFF_ES, ei, out);

    // --- relabel (causal = 0, conf = 1) ---
    k_compact<<<1, 1024>>>(0, batch, out + OFF_CB);
    k_compact<<<1, 1024>>>(1, batch, out + OFF_FB);
    k_fill_batch<<<NN / 256, 256>>>(0, out + OFF_CB);
    k_fill_batch<<<NN / 256, 256>>>(1, out + OFF_FB);
    k_gather_x<<<(NN * 64) / 256, 256>>>(0, g_h, out + OFF_CX);
    k_gather_x<<<(NN * 64) / 256, 256>>>(1, g_h, out + OFF_FX);
    k_ei_rel<<<(2 * EC) / 256, 256>>>(0, out + OFF_CEI);
    k_ei_rel<<<(2 * EC) / 256, 256>>>(1, out + OFF_FEI);
}

// round 2
// speedup vs baseline: 1.3587x; 1.3587x over previous
#include <cuda_runtime.h>
#include <cuda_bf16.h>

typedef unsigned long long ull;

// ---------------- problem constants ----------------
#define NN    65536      // nodes
#define HIDD  256
#define BB    64         // batches
#define EPER  8192       // edges per batch
#define ET    524288     // total edges
#define NRES  4096       // kept edges per batch
#define EC    262144     // total causal (=conf) edges

// ---------------- output offsets (float32 elements) ----------------
#define OFF_CX   0ul
#define OFF_CEI  16777216ul
#define OFF_CW   17301504ul
#define OFF_CB   17563648ul
#define OFF_FX   17629184ul
#define OFF_FEI  34406400ul
#define OFF_FW   34930688ul
#define OFF_FB   35192832ul
#define OFF_ES   35258368ul

// ---------------- scratch ----------------
__device__ float g_t[NN * HIDD];
__device__ float g_u[NN * HIDD];
__device__ float g_h[NN * HIDD];
__device__ int   g_deg[NN + 1];
__device__ int   g_pos[NN];
__device__ int   g_col[ET];
__device__ float g_ssrc[NN];
__device__ float g_sdst[NN];
__device__ int   g_cei[2 * EC];
__device__ int   g_fei[2 * EC];
__device__ int   g_pres_c[NN];
__device__ int   g_pres_f[NN];
__device__ int   g_rank_c[NN];
__device__ int   g_rank_f[NN];
__device__ int   g_list_c[NN];
__device__ int   g_list_f[NN];
__device__ int   g_cnt_c;
__device__ int   g_cnt_f;

// ---------------- f32x2 packed helpers (sm_103a FFMA2) ----------------
__device__ __forceinline__ ull dup2(float x) {
    ull r;
    asm("mov.b64 %0, {%1, %1};" : "=l"(r) : "r"(__float_as_uint(x)));
    return r;
}
__device__ __forceinline__ void fma2(ull& d, ull a, ull b) {
    asm("fma.rn.f32x2 %0, %1, %2, %0;" : "+l"(d) : "l"(a), "l"(b));
}

// ---------------- CSR build ----------------
__global__ void k_zero_misc() {
    int i = blockIdx.x * blockDim.x + threadIdx.x;
    if (i <= NN) g_deg[i] = 0;
    if (i < NN) { g_pres_c[i] = 0; g_pres_f[i] = 0; }
}

__global__ void k_count_deg(const int* __restrict__ ei) {
    int e = blockIdx.x * blockDim.x + threadIdx.x;
    if (e < ET) atomicAdd(&g_deg[ei[e] + 1], 1);
}

// single-block inclusive scan; also writes g_pos
__global__ __launch_bounds__(1024) void k_scan_deg() {
    __shared__ int part[1024];
    const int t = threadIdx.x;
    const int CH = 65;
    int base = t * CH;
    int n = 0;
    if (base < NN + 1) { n = NN + 1 - base; if (n > CH) n = CH; }
    int s = 0;
    for (int i = 0; i < n; i++) s += g_deg[base + i];
    part[t] = s;
    __syncthreads();
    for (int off = 1; off < 1024; off <<= 1) {
        int v = (t >= off) ? part[t - off] : 0;
        __syncthreads();
        part[t] += v;
        __syncthreads();
    }
    int run = part[t] - s;
    for (int i = 0; i < n; i++) {
        run += g_deg[base + i];
        g_deg[base + i] = run;
        if (base + i < NN) g_pos[base + i] = run;
    }
}

__global__ void k_fill_csr(const int* __restrict__ ei) {
    int e = blockIdx.x * blockDim.x + threadIdx.x;
    if (e < ET) {
        int r = ei[e];
        int p = atomicAdd(&g_pos[r], 1);
        g_col[p] = ei[ET + e];
    }
}

// t[v] = h[v] + sum_nb h[nb], MLP-4 neighbor prefetch
__global__ __launch_bounds__(128) void k_agg(const float* __restrict__ hin,
                                             float* __restrict__ tout) {
    int v = blockIdx.x * 2 + (threadIdx.x >> 6);
    int lane = threadIdx.x & 63;
    const float4* H = (const float4*)hin;
    float4 acc = H[(size_t)v * 64 + lane];
    int s = g_deg[v], e = g_deg[v + 1];
    int i = s;
    for (; i + 4 <= e; i += 4) {
        int n0 = g_col[i], n1 = g_col[i + 1], n2 = g_col[i + 2], n3 = g_col[i + 3];
        float4 x0 = H[(size_t)n0 * 64 + lane];
        float4 x1 = H[(size_t)n1 * 64 + lane];
        float4 x2 = H[(size_t)n2 * 64 + lane];
        float4 x3 = H[(size_t)n3 * 64 + lane];
        acc.x += x0.x + x1.x + x2.x + x3.x;
        acc.y += x0.y + x1.y + x2.y + x3.y;
        acc.z += x0.z + x1.z + x2.z + x3.z;
        acc.w += x0.w + x1.w + x2.w + x3.w;
    }
    for (; i < e; i++) {
        int nb = g_col[i];
        float4 x = H[(size_t)nb * 64 + lane];
        acc.x += x.x; acc.y += x.y; acc.z += x.z; acc.w += x.w;
    }
    ((float4*)tout)[(size_t)v * 64 + lane] = acc;
}

// ---------------- GEMM: C = relu(A @ W + bias), A: Mx256, W: 256x256 ----------------
// 128x128 block tile, BK=16, 256 threads, 8x8 micro-tile (4+4 split at stride 64),
// register-double-buffered global loads, FFMA2 packed math.
#define BM 128
#define BN 128
#define BK 16
#define PADA 132   // As row pad (floats), multiple of 4 for 16B-aligned LDS.128

__global__ __launch_bounds__(256, 2) void k_gemm_bias_relu(const float* __restrict__ A,
                                                           const float* __restrict__ W,
                                                           const float* __restrict__ bias,
                                                           float* __restrict__ C) {
    __shared__ float As[BK][PADA];   // transposed A tile: As[k][m]
    __shared__ float Bs[BK][BN];     // Bs[k][n]

    const int bm = blockIdx.x;
    const int bn = blockIdx.y;
    const int t  = threadIdx.x;
    const int tx = t & 15;   // 16 col groups
    const int ty = t >> 4;   // 16 row groups

    // global load indices (2 float4 each for A and B)
    // A: q in {t, t+256}: row = q>>2 (0..127), kk = q&3
    // B: q in {t, t+256}: r = q>>5 (0..15), c4 = q&31
    const int a_row0 = t >> 2,          a_kk0 = t & 3;
    const int a_row1 = (t + 256) >> 2,  a_kk1 = (t + 256) & 3;
    const int b_r0 = t >> 5,            b_c40 = t & 31;
    const int b_r1 = (t + 256) >> 5,    b_c41 = (t + 256) & 31;

    const float* Ab = A + (size_t)(bm * BM) * 256;
    const float* Wb = W + bn * BN;

    ull acc[8][4];
#pragma unroll
    for (int m = 0; m < 8; m++)
#pragma unroll
        for (int n = 0; n < 4; n++) acc[m][n] = 0ull;

    // prologue loads (k0 = 0)
    float4 ra0 = *(const float4*)&Ab[(size_t)a_row0 * 256 + a_kk0 * 4];
    float4 ra1 = *(const float4*)&Ab[(size_t)a_row1 * 256 + a_kk1 * 4];
    float4 rb0 = *(const float4*)&Wb[(size_t)b_r0 * 256 + b_c40 * 4];
    float4 rb1 = *(const float4*)&Wb[(size_t)b_r1 * 256 + b_c41 * 4];

    for (int k0 = 0; k0 < 256; k0 += BK) {
        // store current regs to smem
        As[a_kk0 * 4 + 0][a_row0] = ra0.x;
        As[a_kk0 * 4 + 1][a_row0] = ra0.y;
        As[a_kk0 * 4 + 2][a_row0] = ra0.z;
        As[a_kk0 * 4 + 3][a_row0] = ra0.w;
        As[a_kk1 * 4 + 0][a_row1] = ra1.x;
        As[a_kk1 * 4 + 1][a_row1] = ra1.y;
        As[a_kk1 * 4 + 2][a_row1] = ra1.z;
        As[a_kk1 * 4 + 3][a_row1] = ra1.w;
        *(float4*)&Bs[b_r0][b_c40 * 4] = rb0;
        *(float4*)&Bs[b_r1][b_c41 * 4] = rb1;
        __syncthreads();

        // issue next-tile global loads early (hide latency behind compute)
        if (k0 + BK < 256) {
            int kn = k0 + BK;
            ra0 = *(const float4*)&Ab[(size_t)a_row0 * 256 + kn + a_kk0 * 4];
            ra1 = *(const float4*)&Ab[(size_t)a_row1 * 256 + kn + a_kk1 * 4];
            rb0 = *(const float4*)&Wb[(size_t)(kn + b_r0) * 256 + b_c40 * 4];
            rb1 = *(const float4*)&Wb[(size_t)(kn + b_r1) * 256 + b_c41 * 4];
        }

#pragma unroll
        for (int k = 0; k < BK; k++) {
            float4 a0 = *(const float4*)&As[k][ty * 4];
            float4 a1 = *(const float4*)&As[k][64 + ty * 4];
            const ull* bp0 = (const ull*)&Bs[k][tx * 4];
            const ull* bp1 = (const ull*)&Bs[k][64 + tx * 4];
            ull b0 = bp0[0], b1 = bp0[1], b2 = bp1[0], b3 = bp1[1];
            float av[8] = {a0.x, a0.y, a0.z, a0.w, a1.x, a1.y, a1.z, a1.w};
#pragma unroll
            for (int m = 0; m < 8; m++) {
                ull am = dup2(av[m]);
                fma2(acc[m][0], am, b0);
                fma2(acc[m][1], am, b1);
                fma2(acc[m][2], am, b2);
                fma2(acc[m][3], am, b3);
            }
        }
        __syncthreads();
    }

    // epilogue: bias + relu + store
    float4 bv0 = *(const float4*)&bias[bn * BN + tx * 4];
    float4 bv1 = *(const float4*)&bias[bn * BN + 64 + tx * 4];
#pragma unroll
    for (int m = 0; m < 8; m++) {
        int row = bm * BM + ((m < 4) ? (ty * 4 + m) : (64 + ty * 4 + m - 4));
        float2 p0 = *(float2*)&acc[m][0];
        float2 p1 = *(float2*)&acc[m][1];
        float2 p2 = *(float2*)&acc[m][2];
        float2 p3 = *(float2*)&acc[m][3];
        float4 r0, r1;
        r0.x = fmaxf(p0.x + bv0.x, 0.f);
        r0.y = fmaxf(p0.y + bv0.y, 0.f);
        r0.z = fmaxf(p1.x + bv0.z, 0.f);
        r0.w = fmaxf(p1.y + bv0.w, 0.f);
        r1.x = fmaxf(p2.x + bv1.x, 0.f);
        r1.y = fmaxf(p2.y + bv1.y, 0.f);
        r1.z = fmaxf(p3.x + bv1.z, 0.f);
        r1.w = fmaxf(p3.y + bv1.w, 0.f);
        *(float4*)&C[(size_t)row * 256 + bn * BN + tx * 4] = r0;
        *(float4*)&C[(size_t)row * 256 + bn * BN + 64 + tx * 4] = r1;
    }
}

// ---------------- scores ----------------
__global__ __launch_bounds__(256) void k_score(const float* __restrict__ h,
                                               const float* __restrict__ wsc) {
    int gw = (blockIdx.x * blockDim.x + threadIdx.x) >> 5;
    int lane = threadIdx.x & 31;
    if (gw >= NN) return;
    const float4* H = (const float4*)(h + (size_t)gw * 256);
    const float4* W1 = (const float4*)wsc;
    const float4* W2 = (const float4*)(wsc + 256);
    float s1 = 0.f, s2 = 0.f;
#pragma unroll
    for (int i = lane; i < 64; i += 32) {
        float4 hv = H[i], w1 = W1[i], w2 = W2[i];
        s1 += hv.x * w1.x + hv.y * w1.y + hv.z * w1.z + hv.w * w1.w;
        s2 += hv.x * w2.x + hv.y * w2.y + hv.z * w2.z + hv.w * w2.w;
    }
#pragma unroll
    for (int o = 16; o; o >>= 1) {
        s1 += __shfl_xor_sync(0xffffffffu, s1, o);
        s2 += __shfl_xor_sync(0xffffffffu, s2, o);
    }
    if (lane == 0) { g_ssrc[gw] = s1; g_sdst[gw] = s2; }
}

__global__ void k_edge_score(const int* __restrict__ ei,
                             const float* __restrict__ bsc,
                             float* __restrict__ out) {
    int e = blockIdx.x * blockDim.x + threadIdx.x;
    if (e < ET) {
        out[OFF_ES + e] = g_ssrc[ei[e]] + g_sdst[ei[ET + e]] + bsc[0];
    }
}

// ---------------- per-batch stable sort + split ----------------
__global__ __launch_bounds__(1024) void k_sort_select(const float* __restrict__ es,
                                                      const int* __restrict__ ei,
                                                      float* __restrict__ out) {
    __shared__ unsigned int   kh[EPER];
    __shared__ unsigned short kl[EPER];
    const int b = blockIdx.x;
    const int tid = threadIdx.x;

    for (int i = tid; i < EPER; i += 1024) {
        float s = es[b * EPER + i];
        unsigned u = __float_as_uint(s);
        u = (u & 0x80000000u) ? ~u : (u | 0x80000000u);
        kh[i] = ~u;
        kl[i] = (unsigned short)i;
    }
    __syncthreads();

    for (int k = 2; k <= EPER; k <<= 1) {
        for (int j = k >> 1; j > 0; j >>= 1) {
            for (int i = tid; i < EPER; i += 1024) {
                int l = i ^ j;
                if (l > i) {
                    bool up = ((i & k) == 0);
                    unsigned ah = kh[i], bh = kh[l];
                    unsigned short al = kl[i], bl = kl[l];
                    bool agtb = (ah > bh) || (ah == bh && al > bl);
                    if (agtb == up) {
                        kh[i] = bh; kh[l] = ah;
                        kl[i] = bl; kl[l] = al;
                    }
                }
            }
            __syncthreads();
        }
    }

    for (int i = tid; i < EPER; i += 1024) {
        int idx = kl[i];
        int ge = b * EPER + idx;
        float s = es[ge];
        int r = ei[ge];
        int c = ei[ET + ge];
        if (i < NRES) {
            int p = b * NRES + i;
            out[OFF_CW + p] = s;
            g_cei[p] = r; g_cei[EC + p] = c;
            g_pres_c[r] = 1; g_pres_c[c] = 1;
        } else {
            int p = b * NRES + (i - NRES);
            out[OFF_FW + p] = -s;
            g_fei[p] = r; g_fei[EC + p] = c;
            g_pres_f[r] = 1; g_pres_f[c] = 1;
        }
    }
}

// ---------------- relabel ----------------
__global__ __launch_bounds__(1024) void k_compact(int which,
                                                  const int* __restrict__ batch_in,
                                                  float* __restrict__ out_b) {
    __shared__ int part[1024];
    const int* pres = which ? g_pres_f : g_pres_c;
    int* rank = which ? g_rank_f : g_rank_c;
    int* list = which ? g_list_f : g_list_c;
    int* cnt = which ? &g_cnt_f : &g_cnt_c;

    const int t = threadIdx.x;
    const int base = t * 64;
    int s = 0;
    for (int i = 0; i < 64; i++) s += pres[base + i];
    part[t] = s;
    __syncthreads();
    for (int off = 1; off < 1024; off <<= 1) {
        int v = (t >= off) ? part[t - off] : 0;
        __syncthreads();
        part[t] += v;
        __syncthreads();
    }
    int run = part[t] - s;
    for (int i = 0; i < 64; i++) {
        int v = base + i;
        if (pres[v]) {
            rank[v] = run;
            list[run] = v;
            out_b[run] = (float)batch_in[v];
            run++;
        }
    }
    if (t == 1023) *cnt = part[1023];
}

__global__ void k_fill_batch(int which, float* __restrict__ out_b) {
    int i = blockIdx.x * blockDim.x + threadIdx.x;
    int c = which ? g_cnt_f : g_cnt_c;
    if (i < NN && i >= c) out_b[i] = -1.0f;
}

__global__ void k_gather_x(int which, const float* __restrict__ h,
                           float* __restrict__ outx) {
    int gid = blockIdx.x * blockDim.x + threadIdx.x;
    if (gid >= NN * 64) return;
    int row = gid >> 6;
    int c = gid & 63;
    int cnt = which ? g_cnt_f : g_cnt_c;
    float4 v;
    if (row < cnt) {
        int src = which ? g_list_f[row] : g_list_c[row];
        v = ((const float4*)h)[(size_t)src * 64 + c];
    } else {
        v = make_float4(0.f, 0.f, 0.f, 0.f);
    }
    ((float4*)outx)[gid] = v;
}

__global__ void k_ei_rel(int which, float* __restrict__ dst) {
    int k = blockIdx.x * blockDim.x + threadIdx.x;
    if (k < 2 * EC) {
        const int* eib = which ? g_fei : g_cei;
        const int* rank = which ? g_rank_f : g_rank_c;
        dst[k] = (float)rank[eib[k]];
    }
}

// ---------------- launch ----------------
extern "C" void kernel_launch(void* const* d_in, const int* in_sizes, int n_in,
                              void* d_out, int out_size) {
    (void)in_sizes; (void)n_in; (void)out_size;
    const float* x    = (const float*)d_in[0];
    const int*   ei   = (const int*)d_in[1];
    const int*   batch= (const int*)d_in[2];
    const float* W11  = (const float*)d_in[3];
    const float* b11  = (const float*)d_in[4];
    const float* W12  = (const float*)d_in[5];
    const float* b12  = (const float*)d_in[6];
    const float* W21  = (const float*)d_in[7];
    const float* b21  = (const float*)d_in[8];
    const float* W22  = (const float*)d_in[9];
    const float* b22  = (const float*)d_in[10];
    const float* wsc  = (const float*)d_in[11];
    const float* bsc  = (const float*)d_in[12];
    float* out = (float*)d_out;

    // --- CSR build (launches 0-3) ---
    k_zero_misc<<<(NN + 1 + 255) / 256, 256>>>();
    k_count_deg<<<ET / 256, 256>>>(ei);
    k_scan_deg<<<1, 1024>>>();
    k_fill_csr<<<ET / 256, 256>>>(ei);

    dim3 ggrid(NN / BM, HIDD / BN);

    // --- GIN layer 1 (launch 4 = agg, launch 5 = GEMM -> profiled by ncu) ---
    k_agg<<<NN / 2, 128>>>(x, g_t);
    k_gemm_bias_relu<<<ggrid, 256>>>(g_t, W11, b11, g_u);
    k_gemm_bias_relu<<<ggrid, 256>>>(g_u, W12, b12, g_h);

    // --- GIN layer 2 ---
    k_agg<<<NN / 2, 128>>>(g_h, g_t);
    k_gemm_bias_relu<<<ggrid, 256>>>(g_t, W21, b21, g_u);
    k_gemm_bias_relu<<<ggrid, 256>>>(g_u, W22, b22, g_h);

    // --- edge scores ---
    k_score<<<(NN * 32) / 256, 256>>>(g_h, wsc);
    k_edge_score<<<ET / 256, 256>>>(ei, bsc, out);

    // --- per-batch stable sort + top-k split ---
    k_sort_select<<<BB, 1024>>>(out + OFF_ES, ei, out);

    // --- relabel ---
    k_compact<<<1, 1024>>>(0, batch, out + OFF_CB);
    k_compact<<<1, 1024>>>(1, batch, out + OFF_FB);
    k_fill_batch<<<NN / 256, 256>>>(0, out + OFF_CB);
    k_fill_batch<<<NN / 256, 256>>>(1, out + OFF_FB);
    k_gather_x<<<(NN * 64) / 256, 256>>>(0, g_h, out + OFF_CX);
    k_gather_x<<<(NN * 64) / 256, 256>>>(1, g_h, out + OFF_FX);
    k_ei_rel<<<(2 * EC) / 256, 256>>>(0, out + OFF_CEI);
    k_ei_rel<<<(2 * EC) / 256, 256>>>(1, out + OFF_FEI);
}

// round 3
// speedup vs baseline: 1.3885x; 1.0219x over previous
#include <cuda_runtime.h>
#include <cuda_bf16.h>

typedef unsigned long long ull;

// ---------------- problem constants ----------------
#define NN    65536      // nodes
#define HIDD  256
#define BB    64         // batches
#define EPER  8192       // edges per batch
#define ET    524288     // total edges
#define NRES  4096       // kept edges per batch
#define EC    262144     // total causal (=conf) edges

// ---------------- output offsets (float32 elements) ----------------
#define OFF_CX   0ul
#define OFF_CEI  16777216ul
#define OFF_CW   17301504ul
#define OFF_CB   17563648ul
#define OFF_FX   17629184ul
#define OFF_FEI  34406400ul
#define OFF_FW   34930688ul
#define OFF_FB   35192832ul
#define OFF_ES   35258368ul

// ---------------- scratch ----------------
__device__ float g_t[NN * HIDD];
__device__ float g_u[NN * HIDD];
__device__ float g_h[NN * HIDD];
__device__ int   g_deg[NN + 1];
__device__ int   g_pos[NN];
__device__ int   g_col[ET];
__device__ float g_ssrc[NN];
__device__ float g_sdst[NN];
__device__ int   g_cei[2 * EC];
__device__ int   g_fei[2 * EC];
__device__ int   g_pres_c[NN];
__device__ int   g_pres_f[NN];
__device__ int   g_rank_c[NN];
__device__ int   g_rank_f[NN];
__device__ int   g_list_c[NN];
__device__ int   g_list_f[NN];
__device__ int   g_cnt_c;
__device__ int   g_cnt_f;

// ---------------- f32x2 packed helpers (sm_103a FFMA2) ----------------
__device__ __forceinline__ ull dup2(float x) {
    ull r;
    asm("mov.b64 %0, {%1, %1};" : "=l"(r) : "r"(__float_as_uint(x)));
    return r;
}
__device__ __forceinline__ void fma2(ull& d, ull a, ull b) {
    asm("fma.rn.f32x2 %0, %1, %2, %0;" : "+l"(d) : "l"(a), "l"(b));
}

// ---------------- CSR build ----------------
__global__ void k_zero_misc() {
    int i = blockIdx.x * blockDim.x + threadIdx.x;
    if (i <= NN) g_deg[i] = 0;
    if (i < NN) { g_pres_c[i] = 0; g_pres_f[i] = 0; }
}

__global__ void k_count_deg(const int* __restrict__ ei) {
    int e = blockIdx.x * blockDim.x + threadIdx.x;
    if (e < ET) atomicAdd(&g_deg[ei[e] + 1], 1);
}

// single-block inclusive scan; also writes g_pos
__global__ __launch_bounds__(1024) void k_scan_deg() {
    __shared__ int part[1024];
    const int t = threadIdx.x;
    const int CH = 65;
    int base = t * CH;
    int n = 0;
    if (base < NN + 1) { n = NN + 1 - base; if (n > CH) n = CH; }
    int s = 0;
    for (int i = 0; i < n; i++) s += g_deg[base + i];
    part[t] = s;
    __syncthreads();
    for (int off = 1; off < 1024; off <<= 1) {
        int v = (t >= off) ? part[t - off] : 0;
        __syncthreads();
        part[t] += v;
        __syncthreads();
    }
    int run = part[t] - s;
    for (int i = 0; i < n; i++) {
        run += g_deg[base + i];
        g_deg[base + i] = run;
        if (base + i < NN) g_pos[base + i] = run;
    }
}

__global__ void k_fill_csr(const int* __restrict__ ei) {
    int e = blockIdx.x * blockDim.x + threadIdx.x;
    if (e < ET) {
        int r = ei[e];
        int p = atomicAdd(&g_pos[r], 1);
        g_col[p] = ei[ET + e];
    }
}

// t[v] = h[v] + sum_nb h[nb], MLP-4 neighbor prefetch
__global__ __launch_bounds__(128) void k_agg(const float* __restrict__ hin,
                                             float* __restrict__ tout) {
    int v = blockIdx.x * 2 + (threadIdx.x >> 6);
    int lane = threadIdx.x & 63;
    const float4* H = (const float4*)hin;
    float4 acc = H[(size_t)v * 64 + lane];
    int s = g_deg[v], e = g_deg[v + 1];
    int i = s;
    for (; i + 4 <= e; i += 4) {
        int n0 = g_col[i], n1 = g_col[i + 1], n2 = g_col[i + 2], n3 = g_col[i + 3];
        float4 x0 = H[(size_t)n0 * 64 + lane];
        float4 x1 = H[(size_t)n1 * 64 + lane];
        float4 x2 = H[(size_t)n2 * 64 + lane];
        float4 x3 = H[(size_t)n3 * 64 + lane];
        acc.x += x0.x + x1.x + x2.x + x3.x;
        acc.y += x0.y + x1.y + x2.y + x3.y;
        acc.z += x0.z + x1.z + x2.z + x3.z;
        acc.w += x0.w + x1.w + x2.w + x3.w;
    }
    for (; i < e; i++) {
        int nb = g_col[i];
        float4 x = H[(size_t)nb * 64 + lane];
        acc.x += x.x; acc.y += x.y; acc.z += x.z; acc.w += x.w;
    }
    ((float4*)tout)[(size_t)v * 64 + lane] = acc;
}

// ---------------- GEMM: C = relu(A @ W + bias), A: Mx256, W: 256x256 ----------------
// 128x128 block tile, BK=16, 256 threads, 8x8 micro-tile (4+4 split at stride 64),
// register-staged global loads, FFMA2 packed math. No forced occupancy (avoid spills).
#define BM 128
#define BN 128
#define BK 16
#define PADA 132

__global__ __launch_bounds__(256) void k_gemm_bias_relu(const float* __restrict__ A,
                                                        const float* __restrict__ W,
                                                        const float* __restrict__ bias,
                                                        float* __restrict__ C) {
    __shared__ float As[BK][PADA];   // transposed A tile: As[k][m]
    __shared__ float Bs[BK][BN];     // Bs[k][n]

    const int bm = blockIdx.x;
    const int bn = blockIdx.y;
    const int t  = threadIdx.x;
    const int tx = t & 15;
    const int ty = t >> 4;

    const int a_row0 = t >> 2,          a_kk0 = t & 3;
    const int a_row1 = (t + 256) >> 2,  a_kk1 = (t + 256) & 3;
    const int b_r0 = t >> 5,            b_c40 = t & 31;
    const int b_r1 = (t + 256) >> 5,    b_c41 = (t + 256) & 31;

    const float* Ab = A + (size_t)(bm * BM) * 256;
    const float* Wb = W + bn * BN;

    ull acc[8][4];
#pragma unroll
    for (int m = 0; m < 8; m++)
#pragma unroll
        for (int n = 0; n < 4; n++) acc[m][n] = 0ull;

    float4 ra0 = *(const float4*)&Ab[(size_t)a_row0 * 256 + a_kk0 * 4];
    float4 ra1 = *(const float4*)&Ab[(size_t)a_row1 * 256 + a_kk1 * 4];
    float4 rb0 = *(const float4*)&Wb[(size_t)b_r0 * 256 + b_c40 * 4];
    float4 rb1 = *(const float4*)&Wb[(size_t)b_r1 * 256 + b_c41 * 4];

    for (int k0 = 0; k0 < 256; k0 += BK) {
        As[a_kk0 * 4 + 0][a_row0] = ra0.x;
        As[a_kk0 * 4 + 1][a_row0] = ra0.y;
        As[a_kk0 * 4 + 2][a_row0] = ra0.z;
        As[a_kk0 * 4 + 3][a_row0] = ra0.w;
        As[a_kk1 * 4 + 0][a_row1] = ra1.x;
        As[a_kk1 * 4 + 1][a_row1] = ra1.y;
        As[a_kk1 * 4 + 2][a_row1] = ra1.z;
        As[a_kk1 * 4 + 3][a_row1] = ra1.w;
        *(float4*)&Bs[b_r0][b_c40 * 4] = rb0;
        *(float4*)&Bs[b_r1][b_c41 * 4] = rb1;
        __syncthreads();

        if (k0 + BK < 256) {
            int kn = k0 + BK;
            ra0 = *(const float4*)&Ab[(size_t)a_row0 * 256 + kn + a_kk0 * 4];
            ra1 = *(const float4*)&Ab[(size_t)a_row1 * 256 + kn + a_kk1 * 4];
            rb0 = *(const float4*)&Wb[(size_t)(kn + b_r0) * 256 + b_c40 * 4];
            rb1 = *(const float4*)&Wb[(size_t)(kn + b_r1) * 256 + b_c41 * 4];
        }

#pragma unroll
        for (int k = 0; k < BK; k++) {
            float4 a0 = *(const float4*)&As[k][ty * 4];
            float4 a1 = *(const float4*)&As[k][64 + ty * 4];
            const ull* bp0 = (const ull*)&Bs[k][tx * 4];
            const ull* bp1 = (const ull*)&Bs[k][64 + tx * 4];
            ull b0 = bp0[0], b1 = bp0[1], b2 = bp1[0], b3 = bp1[1];
            float av[8] = {a0.x, a0.y, a0.z, a0.w, a1.x, a1.y, a1.z, a1.w};
#pragma unroll
            for (int m = 0; m < 8; m++) {
                ull am = dup2(av[m]);
                fma2(acc[m][0], am, b0);
                fma2(acc[m][1], am, b1);
                fma2(acc[m][2], am, b2);
                fma2(acc[m][3], am, b3);
            }
        }
        __syncthreads();
    }

    float4 bv0 = *(const float4*)&bias[bn * BN + tx * 4];
    float4 bv1 = *(const float4*)&bias[bn * BN + 64 + tx * 4];
#pragma unroll
    for (int m = 0; m < 8; m++) {
        int row = bm * BM + ((m < 4) ? (ty * 4 + m) : (64 + ty * 4 + m - 4));
        float2 p0 = *(float2*)&acc[m][0];
        float2 p1 = *(float2*)&acc[m][1];
        float2 p2 = *(float2*)&acc[m][2];
        float2 p3 = *(float2*)&acc[m][3];
        float4 r0, r1;
        r0.x = fmaxf(p0.x + bv0.x, 0.f);
        r0.y = fmaxf(p0.y + bv0.y, 0.f);
        r0.z = fmaxf(p1.x + bv0.z, 0.f);
        r0.w = fmaxf(p1.y + bv0.w, 0.f);
        r1.x = fmaxf(p2.x + bv1.x, 0.f);
        r1.y = fmaxf(p2.y + bv1.y, 0.f);
        r1.z = fmaxf(p3.x + bv1.z, 0.f);
        r1.w = fmaxf(p3.y + bv1.w, 0.f);
        *(float4*)&C[(size_t)row * 256 + bn * BN + tx * 4] = r0;
        *(float4*)&C[(size_t)row * 256 + bn * BN + 64 + tx * 4] = r1;
    }
}

// ---------------- scores ----------------
__global__ __launch_bounds__(256) void k_score(const float* __restrict__ h,
                                               const float* __restrict__ wsc) {
    int gw = (blockIdx.x * blockDim.x + threadIdx.x) >> 5;
    int lane = threadIdx.x & 31;
    if (gw >= NN) return;
    const float4* H = (const float4*)(h + (size_t)gw * 256);
    const float4* W1 = (const float4*)wsc;
    const float4* W2 = (const float4*)(wsc + 256);
    float s1 = 0.f, s2 = 0.f;
#pragma unroll
    for (int i = lane; i < 64; i += 32) {
        float4 hv = H[i], w1 = W1[i], w2 = W2[i];
        s1 += hv.x * w1.x + hv.y * w1.y + hv.z * w1.z + hv.w * w1.w;
        s2 += hv.x * w2.x + hv.y * w2.y + hv.z * w2.z + hv.w * w2.w;
    }
#pragma unroll
    for (int o = 16; o; o >>= 1) {
        s1 += __shfl_xor_sync(0xffffffffu, s1, o);
        s2 += __shfl_xor_sync(0xffffffffu, s2, o);
    }
    if (lane == 0) { g_ssrc[gw] = s1; g_sdst[gw] = s2; }
}

__global__ void k_edge_score(const int* __restrict__ ei,
                             const float* __restrict__ bsc,
                             float* __restrict__ out) {
    int e = blockIdx.x * blockDim.x + threadIdx.x;
    if (e < ET) {
        out[OFF_ES + e] = g_ssrc[ei[e]] + g_sdst[ei[ET + e]] + bsc[0];
    }
}

// ---------------- per-batch stable sort + split ----------------
__global__ __launch_bounds__(1024) void k_sort_select(const float* __restrict__ es,
                                                      const int* __restrict__ ei,
                                                      float* __restrict__ out) {
    __shared__ unsigned int   kh[EPER];
    __shared__ unsigned short kl[EPER];
    const int b = blockIdx.x;
    const int tid = threadIdx.x;

    for (int i = tid; i < EPER; i += 1024) {
        float s = es[b * EPER + i];
        unsigned u = __float_as_uint(s);
        u = (u & 0x80000000u) ? ~u : (u | 0x80000000u);
        kh[i] = ~u;
        kl[i] = (unsigned short)i;
    }
    __syncthreads();

    for (int k = 2; k <= EPER; k <<= 1) {
        for (int j = k >> 1; j > 0; j >>= 1) {
            for (int i = tid; i < EPER; i += 1024) {
                int l = i ^ j;
                if (l > i) {
                    bool up = ((i & k) == 0);
                    unsigned ah = kh[i], bh = kh[l];
                    unsigned short al = kl[i], bl = kl[l];
                    bool agtb = (ah > bh) || (ah == bh && al > bl);
                    if (agtb == up) {
                        kh[i] = bh; kh[l] = ah;
                        kl[i] = bl; kl[l] = al;
                    }
                }
            }
            __syncthreads();
        }
    }

    for (int i = tid; i < EPER; i += 1024) {
        int idx = kl[i];
        int ge = b * EPER + idx;
        float s = es[ge];
        int r = ei[ge];
        int c = ei[ET + ge];
        if (i < NRES) {
            int p = b * NRES + i;
            out[OFF_CW + p] = s;
            g_cei[p] = r; g_cei[EC + p] = c;
            g_pres_c[r] = 1; g_pres_c[c] = 1;
        } else {
            int p = b * NRES + (i - NRES);
            out[OFF_FW + p] = -s;
            g_fei[p] = r; g_fei[EC + p] = c;
            g_pres_f[r] = 1; g_pres_f[c] = 1;
        }
    }
}

// ---------------- relabel ----------------
__global__ __launch_bounds__(1024) void k_compact(int which,
                                                  const int* __restrict__ batch_in,
                                                  float* __restrict__ out_b) {
    __shared__ int part[1024];
    const int* pres = which ? g_pres_f : g_pres_c;
    int* rank = which ? g_rank_f : g_rank_c;
    int* list = which ? g_list_f : g_list_c;
    int* cnt = which ? &g_cnt_f : &g_cnt_c;

    const int t = threadIdx.x;
    const int base = t * 64;
    int s = 0;
    for (int i = 0; i < 64; i++) s += pres[base + i];
    part[t] = s;
    __syncthreads();
    for (int off = 1; off < 1024; off <<= 1) {
        int v = (t >= off) ? part[t - off] : 0;
        __syncthreads();
        part[t] += v;
        __syncthreads();
    }
    int run = part[t] - s;
    for (int i = 0; i < 64; i++) {
        int v = base + i;
        if (pres[v]) {
            rank[v] = run;
            list[run] = v;
            out_b[run] = (float)batch_in[v];
            run++;
        }
    }
    if (t == 1023) *cnt = part[1023];
}

__global__ void k_fill_batch(int which, float* __restrict__ out_b) {
    int i = blockIdx.x * blockDim.x + threadIdx.x;
    int c = which ? g_cnt_f : g_cnt_c;
    if (i < NN && i >= c) out_b[i] = -1.0f;
}

__global__ void k_gather_x(int which, const float* __restrict__ h,
                           float* __restrict__ outx) {
    int gid = blockIdx.x * blockDim.x + threadIdx.x;
    if (gid >= NN * 64) return;
    int row = gid >> 6;
    int c = gid & 63;
    int cnt = which ? g_cnt_f : g_cnt_c;
    float4 v;
    if (row < cnt) {
        int src = which ? g_list_f[row] : g_list_c[row];
        v = ((const float4*)h)[(size_t)src * 64 + c];
    } else {
        v = make_float4(0.f, 0.f, 0.f, 0.f);
    }
    ((float4*)outx)[gid] = v;
}

__global__ void k_ei_rel(int which, float* __restrict__ dst) {
    int k = blockIdx.x * blockDim.x + threadIdx.x;
    if (k < 2 * EC) {
        const int* eib = which ? g_fei : g_cei;
        const int* rank = which ? g_rank_f : g_rank_c;
        dst[k] = (float)rank[eib[k]];
    }
}

// ---------------- launch ----------------
extern "C" void kernel_launch(void* const* d_in, const int* in_sizes, int n_in,
                              void* d_out, int out_size) {
    (void)in_sizes; (void)n_in; (void)out_size;
    const float* x    = (const float*)d_in[0];
    const int*   ei   = (const int*)d_in[1];
    const int*   batch= (const int*)d_in[2];
    const float* W11  = (const float*)d_in[3];
    const float* b11  = (const float*)d_in[4];
    const float* W12  = (const float*)d_in[5];
    const float* b12  = (const float*)d_in[6];
    const float* W21  = (const float*)d_in[7];
    const float* b21  = (const float*)d_in[8];
    const float* W22  = (const float*)d_in[9];
    const float* b22  = (const float*)d_in[10];
    const float* wsc  = (const float*)d_in[11];
    const float* bsc  = (const float*)d_in[12];
    float* out = (float*)d_out;

    // --- CSR build (launches 0-2) ---
    k_zero_misc<<<(NN + 1 + 255) / 256, 256>>>();
    k_count_deg<<<ET / 256, 256>>>(ei);
    k_scan_deg<<<1, 1024>>>();

    // --- launch index 3: deterministic PROFILING PROBE of the GEMM ---
    // (~1-wave grid; reads input x + W11, writes g_u which is fully
    //  overwritten by the real layer-1 GEMM below)
    {
        dim3 pg(64, HIDD / BN);
        k_gemm_bias_relu<<<pg, 256>>>(x, W11, b11, g_u);
    }

    k_fill_csr<<<ET / 256, 256>>>(ei);

    dim3 ggrid(NN / BM, HIDD / BN);

    // --- GIN layer 1 ---
    k_agg<<<NN / 2, 128>>>(x, g_t);
    k_gemm_bias_relu<<<ggrid, 256>>>(g_t, W11, b11, g_u);
    k_gemm_bias_relu<<<ggrid, 256>>>(g_u, W12, b12, g_h);

    // --- GIN layer 2 ---
    k_agg<<<NN / 2, 128>>>(g_h, g_t);
    k_gemm_bias_relu<<<ggrid, 256>>>(g_t, W21, b21, g_u);
    k_gemm_bias_relu<<<ggrid, 256>>>(g_u, W22, b22, g_h);

    // --- edge scores ---
    k_score<<<(NN * 32) / 256, 256>>>(g_h, wsc);
    k_edge_score<<<ET / 256, 256>>>(ei, bsc, out);

    // --- per-batch stable sort + top-k split ---
    k_sort_select<<<BB, 1024>>>(out + OFF_ES, ei, out);

    // --- relabel ---
    k_compact<<<1, 1024>>>(0, batch, out + OFF_CB);
    k_compact<<<1, 1024>>>(1, batch, out + OFF_FB);
    k_fill_batch<<<NN / 256, 256>>>(0, out + OFF_CB);
    k_fill_batch<<<NN / 256, 256>>>(1, out + OFF_FB);
    k_gather_x<<<(NN * 64) / 256, 256>>>(0, g_h, out + OFF_CX);
    k_gather_x<<<(NN * 64) / 256, 256>>>(1, g_h, out + OFF_FX);
    k_ei_rel<<<(2 * EC) / 256, 256>>>(0, out + OFF_CEI);
    k_ei_rel<<<(2 * EC) / 256, 256>>>(1, out + OFF_FEI);
}

// round 4
// speedup vs baseline: 1.5125x; 1.0894x over previous
#include <cuda_runtime.h>
#include <cuda_bf16.h>

typedef unsigned long long ull;

// ---------------- problem constants ----------------
#define NN    65536
#define HIDD  256
#define BB    64
#define EPER  8192
#define ET    524288
#define NRES  4096
#define EC    262144

// ---------------- output offsets (float32 elements) ----------------
#define OFF_CX   0ul
#define OFF_CEI  16777216ul
#define OFF_CW   17301504ul
#define OFF_CB   17563648ul
#define OFF_FX   17629184ul
#define OFF_FEI  34406400ul
#define OFF_FW   34930688ul
#define OFF_FB   35192832ul
#define OFF_ES   35258368ul

// ---------------- scratch (zero-initialized at module load) ----------------
__device__ float g_t[NN * HIDD];
__device__ float g_u[NN * HIDD];
__device__ float g_h[NN * HIDD];
__device__ int   g_deg[NN + 1];   // must be 0 at entry; re-zeroed at tail
__device__ int   g_pos[NN];
__device__ int   g_col[ET];
__device__ float g_ssrc[NN];
__device__ float g_sdst[NN];
__device__ int   g_cei[2 * EC];
__device__ int   g_fei[2 * EC];
__device__ int   g_pres_c[NN];    // must be 0 at entry; re-zeroed at tail
__device__ int   g_pres_f[NN];
__device__ int   g_rank_c[NN];
__device__ int   g_rank_f[NN];
__device__ int   g_list_c[NN];
__device__ int   g_list_f[NN];
__device__ int   g_cnt_c;
__device__ int   g_cnt_f;

// ---------------- f32x2 FFMA2 ----------------
__device__ __forceinline__ void fma2(ull& d, ull a, ull b) {
    asm("fma.rn.f32x2 %0, %1, %2, %0;" : "+l"(d) : "l"(a), "l"(b));
}

// ---------------- CSR build ----------------
__global__ void k_count_deg(const int* __restrict__ ei) {
    int e = blockIdx.x * blockDim.x + threadIdx.x;
    if (e < ET) atomicAdd(&g_deg[ei[e] + 1], 1);
}

__global__ __launch_bounds__(1024) void k_scan_deg() {
    __shared__ int part[1024];
    const int t = threadIdx.x;
    const int CH = 65;
    int base = t * CH;
    int n = 0;
    if (base < NN + 1) { n = NN + 1 - base; if (n > CH) n = CH; }
    int s = 0;
    for (int i = 0; i < n; i++) s += g_deg[base + i];
    part[t] = s;
    __syncthreads();
    for (int off = 1; off < 1024; off <<= 1) {
        int v = (t >= off) ? part[t - off] : 0;
        __syncthreads();
        part[t] += v;
        __syncthreads();
    }
    int run = part[t] - s;
    for (int i = 0; i < n; i++) {
        run += g_deg[base + i];
        g_deg[base + i] = run;
        if (base + i < NN) g_pos[base + i] = run;
    }
}

__global__ void k_fill_csr(const int* __restrict__ ei) {
    int e = blockIdx.x * blockDim.x + threadIdx.x;
    if (e < ET) {
        int r = ei[e];
        int p = atomicAdd(&g_pos[r], 1);
        g_col[p] = ei[ET + e];
    }
}

// t[v] = h[v] + sum_nb h[nb]
__global__ __launch_bounds__(128) void k_agg(const float* __restrict__ hin,
                                             float* __restrict__ tout) {
    int v = blockIdx.x * 2 + (threadIdx.x >> 6);
    int lane = threadIdx.x & 63;
    const float4* H = (const float4*)hin;
    float4 acc = H[(size_t)v * 64 + lane];
    int s = g_deg[v], e = g_deg[v + 1];
    int i = s;
    for (; i + 4 <= e; i += 4) {
        int n0 = g_col[i], n1 = g_col[i + 1], n2 = g_col[i + 2], n3 = g_col[i + 3];
        float4 x0 = H[(size_t)n0 * 64 + lane];
        float4 x1 = H[(size_t)n1 * 64 + lane];
        float4 x2 = H[(size_t)n2 * 64 + lane];
        float4 x3 = H[(size_t)n3 * 64 + lane];
        acc.x += x0.x + x1.x + x2.x + x3.x;
        acc.y += x0.y + x1.y + x2.y + x3.y;
        acc.z += x0.z + x1.z + x2.z + x3.z;
        acc.w += x0.w + x1.w + x2.w + x3.w;
    }
    for (; i < e; i++) {
        int nb = g_col[i];
        float4 x = H[(size_t)nb * 64 + lane];
        acc.x += x.x; acc.y += x.y; acc.z += x.z; acc.w += x.w;
    }
    ((float4*)tout)[(size_t)v * 64 + lane] = acc;
}

// ---------------- GEMM: C = relu(A @ W + bias) ----------------
// 128x128 tile, BK=16, 256 threads, 8x8 micro-tile.
// A stored transposed+DUPLICATED in smem (LDS.128 -> ready (a,a) f32x2 pairs),
// B straight (LDS.128 -> natural (b_n,b_n+1) pairs). Zero dup MOVs in loop.
// 2 CTAs/SM via launch_bounds(256,2).
#define BM 128
#define BN 128
#define BK 16
#define ASD_W 260   // 2*BM + 4 pad (keeps 16B alignment, staggers banks per k)

__global__ __launch_bounds__(256, 2) void k_gemm_bias_relu(const float* __restrict__ A,
                                                           const float* __restrict__ W,
                                                           const float* __restrict__ bias,
                                                           float* __restrict__ C) {
    __shared__ float Asd[BK][ASD_W];   // Asd[k][2m]=Asd[k][2m+1]=A[m][k]
    __shared__ float Bs[BK][BN];       // Bs[k][n]

    const int bm = blockIdx.x;
    const int bn = blockIdx.y;
    const int t  = threadIdx.x;
    const int tx = t & 15;
    const int ty = t >> 4;

    const int a_row0 = t >> 2,          a_kk0 = (t & 3) * 4;
    const int a_row1 = a_row0 + 64;     // (t+256)>>2 = t>>2 + 64, kk same
    const int b_r0 = t >> 5,            b_c0 = (t & 31) * 4;
    const int b_r1 = b_r0 + 8;

    const float* Ab = A + (size_t)(bm * BM) * 256;
    const float* Wb = W + bn * BN;

    ull acc[8][4];
#pragma unroll
    for (int m = 0; m < 8; m++)
#pragma unroll
        for (int n = 0; n < 4; n++) acc[m][n] = 0ull;

    float4 ra0 = *(const float4*)&Ab[(size_t)a_row0 * 256 + a_kk0];
    float4 ra1 = *(const float4*)&Ab[(size_t)a_row1 * 256 + a_kk0];
    float4 rb0 = *(const float4*)&Wb[(size_t)b_r0 * 256 + b_c0];
    float4 rb1 = *(const float4*)&Wb[(size_t)b_r1 * 256 + b_c0];

    for (int k0 = 0; k0 < 256; k0 += BK) {
        // A: transpose + duplicate into smem (STS.64 of (v,v))
        *(float2*)&Asd[a_kk0 + 0][2 * a_row0] = make_float2(ra0.x, ra0.x);
        *(float2*)&Asd[a_kk0 + 1][2 * a_row0] = make_float2(ra0.y, ra0.y);
        *(float2*)&Asd[a_kk0 + 2][2 * a_row0] = make_float2(ra0.z, ra0.z);
        *(float2*)&Asd[a_kk0 + 3][2 * a_row0] = make_float2(ra0.w, ra0.w);
        *(float2*)&Asd[a_kk0 + 0][2 * a_row1] = make_float2(ra1.x, ra1.x);
        *(float2*)&Asd[a_kk0 + 1][2 * a_row1] = make_float2(ra1.y, ra1.y);
        *(float2*)&Asd[a_kk0 + 2][2 * a_row1] = make_float2(ra1.z, ra1.z);
        *(float2*)&Asd[a_kk0 + 3][2 * a_row1] = make_float2(ra1.w, ra1.w);
        *(float4*)&Bs[b_r0][b_c0] = rb0;
        *(float4*)&Bs[b_r1][b_c0] = rb1;
        __syncthreads();

        if (k0 + BK < 256) {
            int kn = k0 + BK;
            ra0 = *(const float4*)&Ab[(size_t)a_row0 * 256 + kn + a_kk0];
            ra1 = *(const float4*)&Ab[(size_t)a_row1 * 256 + kn + a_kk0];
            rb0 = *(const float4*)&Wb[(size_t)(kn + b_r0) * 256 + b_c0];
            rb1 = *(const float4*)&Wb[(size_t)(kn + b_r1) * 256 + b_c0];
        }

#pragma unroll
        for (int k = 0; k < BK; k++) {
            // a dup pairs: rows 4ty..4ty+3 and 64+4ty..64+4ty+3
            ulonglong2 A01 = *(const ulonglong2*)&Asd[k][8 * ty];
            ulonglong2 A23 = *(const ulonglong2*)&Asd[k][8 * ty + 4];
            ulonglong2 A45 = *(const ulonglong2*)&Asd[k][128 + 8 * ty];
            ulonglong2 A67 = *(const ulonglong2*)&Asd[k][128 + 8 * ty + 4];
            // b natural pairs: cols 4tx..4tx+3 and 64+4tx..64+4tx+3
            ulonglong2 B0 = *(const ulonglong2*)&Bs[k][4 * tx];
            ulonglong2 B1 = *(const ulonglong2*)&Bs[k][64 + 4 * tx];
            ull av[8] = {A01.x, A01.y, A23.x, A23.y, A45.x, A45.y, A67.x, A67.y};
#pragma unroll
            for (int m = 0; m < 8; m++) {
                fma2(acc[m][0], av[m], B0.x);
                fma2(acc[m][1], av[m], B0.y);
                fma2(acc[m][2], av[m], B1.x);
                fma2(acc[m][3], av[m], B1.y);
            }
        }
        __syncthreads();
    }

    float4 bv0 = *(const float4*)&bias[bn * BN + tx * 4];
    float4 bv1 = *(const float4*)&bias[bn * BN + 64 + tx * 4];
#pragma unroll
    for (int m = 0; m < 8; m++) {
        int row = bm * BM + ((m < 4) ? (ty * 4 + m) : (64 + ty * 4 + m - 4));
        float2 p0 = *(float2*)&acc[m][0];
        float2 p1 = *(float2*)&acc[m][1];
        float2 p2 = *(float2*)&acc[m][2];
        float2 p3 = *(float2*)&acc[m][3];
        float4 r0, r1;
        r0.x = fmaxf(p0.x + bv0.x, 0.f);
        r0.y = fmaxf(p0.y + bv0.y, 0.f);
        r0.z = fmaxf(p1.x + bv0.z, 0.f);
        r0.w = fmaxf(p1.y + bv0.w, 0.f);
        r1.x = fmaxf(p2.x + bv1.x, 0.f);
        r1.y = fmaxf(p2.y + bv1.y, 0.f);
        r1.z = fmaxf(p3.x + bv1.z, 0.f);
        r1.w = fmaxf(p3.y + bv1.w, 0.f);
        *(float4*)&C[(size_t)row * 256 + bn * BN + tx * 4] = r0;
        *(float4*)&C[(size_t)row * 256 + bn * BN + 64 + tx * 4] = r1;
    }
}

// ---------------- scores ----------------
__global__ __launch_bounds__(256) void k_score(const float* __restrict__ h,
                                               const float* __restrict__ wsc) {
    int gw = (blockIdx.x * blockDim.x + threadIdx.x) >> 5;
    int lane = threadIdx.x & 31;
    if (gw >= NN) return;
    const float4* H = (const float4*)(h + (size_t)gw * 256);
    const float4* W1 = (const float4*)wsc;
    const float4* W2 = (const float4*)(wsc + 256);
    float s1 = 0.f, s2 = 0.f;
#pragma unroll
    for (int i = lane; i < 64; i += 32) {
        float4 hv = H[i], w1 = W1[i], w2 = W2[i];
        s1 += hv.x * w1.x + hv.y * w1.y + hv.z * w1.z + hv.w * w1.w;
        s2 += hv.x * w2.x + hv.y * w2.y + hv.z * w2.z + hv.w * w2.w;
    }
#pragma unroll
    for (int o = 16; o; o >>= 1) {
        s1 += __shfl_xor_sync(0xffffffffu, s1, o);
        s2 += __shfl_xor_sync(0xffffffffu, s2, o);
    }
    if (lane == 0) { g_ssrc[gw] = s1; g_sdst[gw] = s2; }
}

__global__ void k_edge_score(const int* __restrict__ ei,
                             const float* __restrict__ bsc,
                             float* __restrict__ out) {
    int e = blockIdx.x * blockDim.x + threadIdx.x;
    if (e < ET) {
        out[OFF_ES + e] = g_ssrc[ei[e]] + g_sdst[ei[ET + e]] + bsc[0];
    }
}

// ---------------- per-batch stable sort + split ----------------
__global__ __launch_bounds__(1024) void k_sort_select(const float* __restrict__ es,
                                                      const int* __restrict__ ei,
                                                      float* __restrict__ out) {
    __shared__ unsigned int   kh[EPER];
    __shared__ unsigned short kl[EPER];
    const int b = blockIdx.x;
    const int tid = threadIdx.x;

    for (int i = tid; i < EPER; i += 1024) {
        float s = es[b * EPER + i];
        unsigned u = __float_as_uint(s);
        u = (u & 0x80000000u) ? ~u : (u | 0x80000000u);
        kh[i] = ~u;
        kl[i] = (unsigned short)i;
    }
    __syncthreads();

    for (int k = 2; k <= EPER; k <<= 1) {
        for (int j = k >> 1; j > 0; j >>= 1) {
            for (int i = tid; i < EPER; i += 1024) {
                int l = i ^ j;
                if (l > i) {
                    bool up = ((i & k) == 0);
                    unsigned ah = kh[i], bh = kh[l];
                    unsigned short al = kl[i], bl = kl[l];
                    bool agtb = (ah > bh) || (ah == bh && al > bl);
                    if (agtb == up) {
                        kh[i] = bh; kh[l] = ah;
                        kl[i] = bl; kl[l] = al;
                    }
                }
            }
            __syncthreads();
        }
    }

    for (int i = tid; i < EPER; i += 1024) {
        int idx = kl[i];
        int ge = b * EPER + idx;
        float s = es[ge];
        int r = ei[ge];
        int c = ei[ET + ge];
        if (i < NRES) {
            int p = b * NRES + i;
            out[OFF_CW + p] = s;
            g_cei[p] = r; g_cei[EC + p] = c;
            g_pres_c[r] = 1; g_pres_c[c] = 1;
        } else {
            int p = b * NRES + (i - NRES);
            out[OFF_FW + p] = -s;
            g_fei[p] = r; g_fei[EC + p] = c;
            g_pres_f[r] = 1; g_pres_f[c] = 1;
        }
    }
}

// ---------------- relabel: compact + batch fill, 2 blocks (which = blockIdx.x) ----------------
__global__ __launch_bounds__(1024) void k_compact(const int* __restrict__ batch_in,
                                                  float* __restrict__ out) {
    __shared__ int part[1024];
    const int which = blockIdx.x;
    const int* pres = which ? g_pres_f : g_pres_c;
    int* rank = which ? g_rank_f : g_rank_c;
    int* list = which ? g_list_f : g_list_c;
    int* cnt = which ? &g_cnt_f : &g_cnt_c;
    float* out_b = out + (which ? OFF_FB : OFF_CB);

    const int t = threadIdx.x;
    const int base = t * 64;
    int s = 0;
    for (int i = 0; i < 64; i++) s += pres[base + i];
    part[t] = s;
    __syncthreads();
    for (int off = 1; off < 1024; off <<= 1) {
        int v = (t >= off) ? part[t - off] : 0;
        __syncthreads();
        part[t] += v;
        __syncthreads();
    }
    int total = part[1023];
    int run = part[t] - s;
    for (int i = 0; i < 64; i++) {
        int v = base + i;
        if (pres[v]) {
            rank[v] = run;
            list[run] = v;
            out_b[run] = (float)batch_in[v];
            run++;
        }
    }
    // batch fill for positions >= total
    for (int i = 0; i < 64; i++) {
        int p = base + i;
        if (p >= total) out_b[p] = -1.0f;
    }
    if (t == 1023) *cnt = total;
}

__global__ void k_gather_x(const float* __restrict__ h, float* __restrict__ out) {
    int gid = blockIdx.x * blockDim.x + threadIdx.x;
    int which = blockIdx.y;
    if (gid >= NN * 64) return;
    int row = gid >> 6;
    int c = gid & 63;
    int cnt = which ? g_cnt_f : g_cnt_c;
    float4 v;
    if (row < cnt) {
        int src = which ? g_list_f[row] : g_list_c[row];
        v = ((const float4*)h)[(size_t)src * 64 + c];
    } else {
        v = make_float4(0.f, 0.f, 0.f, 0.f);
    }
    float* outx = out + (which ? OFF_FX : OFF_CX);
    ((float4*)outx)[gid] = v;
}

__global__ void k_ei_rel(float* __restrict__ out) {
    int k = blockIdx.x * blockDim.x + threadIdx.x;
    int which = blockIdx.y;
    if (k < 2 * EC) {
        const int* eib = which ? g_fei : g_cei;
        const int* rank = which ? g_rank_f : g_rank_c;
        float* dst = out + (which ? OFF_FEI : OFF_CEI);
        dst[k] = (float)rank[eib[k]];
    }
}

// tail: restore zero-state invariant for next call
__global__ void k_rezero() {
    int i = blockIdx.x * blockDim.x + threadIdx.x;
    if (i <= NN) g_deg[i] = 0;
    if (i < NN) { g_pres_c[i] = 0; g_pres_f[i] = 0; }
}

// ---------------- launch ----------------
extern "C" void kernel_launch(void* const* d_in, const int* in_sizes, int n_in,
                              void* d_out, int out_size) {
    (void)in_sizes; (void)n_in; (void)out_size;
    const float* x    = (const float*)d_in[0];
    const int*   ei   = (const int*)d_in[1];
    const int*   batch= (const int*)d_in[2];
    const float* W11  = (const float*)d_in[3];
    const float* b11  = (const float*)d_in[4];
    const float* W12  = (const float*)d_in[5];
    const float* b12  = (const float*)d_in[6];
    const float* W21  = (const float*)d_in[7];
    const float* b21  = (const float*)d_in[8];
    const float* W22  = (const float*)d_in[9];
    const float* b22  = (const float*)d_in[10];
    const float* wsc  = (const float*)d_in[11];
    const float* bsc  = (const float*)d_in[12];
    float* out = (float*)d_out;

    // g_deg / pres arrays are zero at entry (static init on first call,
    // k_rezero tail on subsequent calls).
    k_count_deg<<<ET / 256, 256>>>(ei);                 // 0
    k_scan_deg<<<1, 1024>>>();                          // 1
    k_fill_csr<<<ET / 256, 256>>>(ei);                  // 2

    dim3 ggrid(NN / BM, HIDD / BN);

    k_agg<<<NN / 2, 128>>>(x, g_t);                     // 3  <- ncu capture
    k_gemm_bias_relu<<<ggrid, 256>>>(g_t, W11, b11, g_u);   // 4
    k_gemm_bias_relu<<<ggrid, 256>>>(g_u, W12, b12, g_h);   // 5

    k_agg<<<NN / 2, 128>>>(g_h, g_t);                   // 6
    k_gemm_bias_relu<<<ggrid, 256>>>(g_t, W21, b21, g_u);   // 7
    k_gemm_bias_relu<<<ggrid, 256>>>(g_u, W22, b22, g_h);   // 8

    k_score<<<(NN * 32) / 256, 256>>>(g_h, wsc);        // 9
    k_edge_score<<<ET / 256, 256>>>(ei, bsc, out);      // 10

    k_sort_select<<<BB, 1024>>>(out + OFF_ES, ei, out); // 11

    k_compact<<<2, 1024>>>(batch, out);                 // 12
    k_gather_x<<<dim3((NN * 64) / 256, 2), 256>>>(g_h, out);  // 13
    k_ei_rel<<<dim3((2 * EC) / 256, 2), 256>>>(out);    // 14

    k_rezero<<<(NN + 256) / 256, 256>>>();              // 15
}